// round 1
// baseline (speedup 1.0000x reference)
#include <cuda_runtime.h>
#include <cstdint>

#define L_DIM 4096
#define B_DIM 4
#define E_DIM 1024
#define H_DIM 16
#define HD 64
#define NH 64            // B*H
#define M_TOT 16384      // L*B
#define EPS_F 1e-4f
#define ANG_C 3.83495196971410283e-4f   // (pi/2)/4096
#define NCHUNK 8

// ---------------- scratch (device globals; no allocs allowed) ----------------
__device__ float g_q[NH * L_DIM * HD];                 // relu(Q) per head-major
__device__ float g_k[NH * L_DIM * HD];                 // relu(K)
__device__ float g_v[NH * L_DIM * HD];                 // V
__device__ float g_kv_part[NH * NCHUNK * 2 * HD * HD]; // per-chunk partial kv (sin/cos)
__device__ float g_ks_part[NH * NCHUNK * 2 * HD];      // per-chunk partial ksum

__device__ __forceinline__ unsigned f2tf32(float x) {
    unsigned r;
    asm("cvt.rna.tf32.f32 %0, %1;" : "=r"(r) : "f"(x));
    return r;
}

__device__ __forceinline__ void mma_tf32(float c[4],
                                         unsigned a0, unsigned a1, unsigned a2, unsigned a3,
                                         unsigned b0, unsigned b1) {
    asm volatile(
        "mma.sync.aligned.m16n8k8.row.col.f32.tf32.tf32.f32 "
        "{%0,%1,%2,%3}, {%4,%5,%6,%7}, {%8,%9}, {%0,%1,%2,%3};\n"
        : "+f"(c[0]), "+f"(c[1]), "+f"(c[2]), "+f"(c[3])
        : "r"(a0), "r"(a1), "r"(a2), "r"(a3), "r"(b0), "r"(b1));
}

// ---------------- Phase 1: fused QKV projection ----------------
// Y = X @ W^T + b ; X: (M_TOT, E) row-major, W: (E, E) row-major (so both K-major).
// Epilogue: relu (Q,K only) + scatter into [head][l][hd] layout.
__global__ __launch_bounds__(256, 1) void gemm_qkv(
    const float* __restrict__ Xq, const float* __restrict__ Xk, const float* __restrict__ Xv,
    const float* __restrict__ Wq, const float* __restrict__ Wk, const float* __restrict__ Wv,
    const float* __restrict__ bq, const float* __restrict__ bk, const float* __restrict__ bv)
{
    __shared__ float As[128][36];   // [m][k], pad 4 -> conflict-free frag loads
    __shared__ float Bs[128][36];   // [n][k]

    const int z = blockIdx.z;
    const float* X    = (z == 0) ? Xq : (z == 1) ? Xk : Xv;
    const float* W    = (z == 0) ? Wq : (z == 1) ? Wk : Wv;
    const float* bias = (z == 0) ? bq : (z == 1) ? bk : bv;
    float* dst        = (z == 0) ? g_q : (z == 1) ? g_k : g_v;
    const bool do_relu = (z < 2);

    const int m0 = blockIdx.y * 128;
    const int n0 = blockIdx.x * 128;
    const int t = threadIdx.x;
    const int lane = t & 31, warp = t >> 5;
    const int wm = (warp & 1) * 64, wn = (warp >> 1) * 32;
    const int gid = lane >> 2, tig = lane & 3;

    const int lr = t >> 3;          // 0..31 (row within 32-row group)
    const int lc = (t & 7) * 4;     // 0..28 (k offset, float4)
    const float* Ag = X + (size_t)(m0 + lr) * E_DIM + lc;
    const float* Bg = W + (size_t)(n0 + lr) * E_DIM + lc;

    float acc[4][4][4];
#pragma unroll
    for (int i = 0; i < 4; ++i)
#pragma unroll
        for (int j = 0; j < 4; ++j)
#pragma unroll
            for (int e = 0; e < 4; ++e) acc[i][j][e] = 0.f;

    float4 na[4], nb[4];
#pragma unroll
    for (int i = 0; i < 4; ++i) {
        na[i] = *(const float4*)(Ag + (size_t)i * 32 * E_DIM);
        nb[i] = *(const float4*)(Bg + (size_t)i * 32 * E_DIM);
    }
#pragma unroll
    for (int i = 0; i < 4; ++i) {
        As[lr + i * 32][lc + 0] = __uint_as_float(f2tf32(na[i].x));
        As[lr + i * 32][lc + 1] = __uint_as_float(f2tf32(na[i].y));
        As[lr + i * 32][lc + 2] = __uint_as_float(f2tf32(na[i].z));
        As[lr + i * 32][lc + 3] = __uint_as_float(f2tf32(na[i].w));
        Bs[lr + i * 32][lc + 0] = __uint_as_float(f2tf32(nb[i].x));
        Bs[lr + i * 32][lc + 1] = __uint_as_float(f2tf32(nb[i].y));
        Bs[lr + i * 32][lc + 2] = __uint_as_float(f2tf32(nb[i].z));
        Bs[lr + i * 32][lc + 3] = __uint_as_float(f2tf32(nb[i].w));
    }
    __syncthreads();

#pragma unroll 1
    for (int kt = 0; kt < 32; ++kt) {
        if (kt < 31) {
#pragma unroll
            for (int i = 0; i < 4; ++i) {
                na[i] = *(const float4*)(Ag + (size_t)(kt + 1) * 32 + (size_t)i * 32 * E_DIM);
                nb[i] = *(const float4*)(Bg + (size_t)(kt + 1) * 32 + (size_t)i * 32 * E_DIM);
            }
        }
#pragma unroll
        for (int k8 = 0; k8 < 4; ++k8) {
            const int kk = k8 * 8;
            unsigned af[4][4], bf[4][2];
#pragma unroll
            for (int mf = 0; mf < 4; ++mf) {
                const int r = wm + mf * 16 + gid;
                af[mf][0] = __float_as_uint(As[r][kk + tig]);
                af[mf][1] = __float_as_uint(As[r + 8][kk + tig]);
                af[mf][2] = __float_as_uint(As[r][kk + tig + 4]);
                af[mf][3] = __float_as_uint(As[r + 8][kk + tig + 4]);
            }
#pragma unroll
            for (int nf = 0; nf < 4; ++nf) {
                const int cb = wn + nf * 8 + gid;
                bf[nf][0] = __float_as_uint(Bs[cb][kk + tig]);
                bf[nf][1] = __float_as_uint(Bs[cb][kk + tig + 4]);
            }
#pragma unroll
            for (int mf = 0; mf < 4; ++mf)
#pragma unroll
                for (int nf = 0; nf < 4; ++nf)
                    mma_tf32(acc[mf][nf], af[mf][0], af[mf][1], af[mf][2], af[mf][3],
                             bf[nf][0], bf[nf][1]);
        }
        __syncthreads();
        if (kt < 31) {
#pragma unroll
            for (int i = 0; i < 4; ++i) {
                As[lr + i * 32][lc + 0] = __uint_as_float(f2tf32(na[i].x));
                As[lr + i * 32][lc + 1] = __uint_as_float(f2tf32(na[i].y));
                As[lr + i * 32][lc + 2] = __uint_as_float(f2tf32(na[i].z));
                As[lr + i * 32][lc + 3] = __uint_as_float(f2tf32(na[i].w));
                Bs[lr + i * 32][lc + 0] = __uint_as_float(f2tf32(nb[i].x));
                Bs[lr + i * 32][lc + 1] = __uint_as_float(f2tf32(nb[i].y));
                Bs[lr + i * 32][lc + 2] = __uint_as_float(f2tf32(nb[i].z));
                Bs[lr + i * 32][lc + 3] = __uint_as_float(f2tf32(nb[i].w));
            }
            __syncthreads();
        }
    }

    // epilogue: bias + relu + scatter to [head][l][hd]
#pragma unroll
    for (int mf = 0; mf < 4; ++mf) {
#pragma unroll
        for (int nf = 0; nf < 4; ++nf) {
            const int row = m0 + wm + mf * 16 + gid;
            const int col = n0 + wn + nf * 8 + tig * 2;
#pragma unroll
            for (int e = 0; e < 4; ++e) {
                const int r = row + ((e >= 2) ? 8 : 0);
                const int cc = col + (e & 1);
                float v = acc[mf][nf][e] + __ldg(&bias[cc]);
                if (do_relu) v = fmaxf(v, 0.f);
                const int l = r >> 2, bb = r & 3;
                const int hh = cc >> 6, hd = cc & 63;
                const int head = bb * H_DIM + hh;
                dst[((size_t)head << 18) + ((size_t)l << 6) + (size_t)hd] = v;
            }
        }
    }
}

// ---------------- Phase 2: kv = k_^T v and ksum, per head, chunked over L ----------------
// grid (NH, NCHUNK), 256 threads. Each thread owns 4d x 4m accumulators (x sin/cos).
__global__ __launch_bounds__(256, 4) void kv_kernel() {
    const int h = blockIdx.x, ch = blockIdx.y;
    const float* kp = g_k + (size_t)h * (L_DIM * HD);
    const float* vp = g_v + (size_t)h * (L_DIM * HD);
    __shared__ float ks[8 * 64];
    __shared__ float vs[8 * 64];

    const int t = threadIdx.x;
    const int d0 = (t >> 4) * 4;     // 0..60
    const int m0 = (t & 15) * 4;     // 0..60

    float accs[4][4], accc[4][4];
    float sas[4] = {0.f, 0.f, 0.f, 0.f}, sac[4] = {0.f, 0.f, 0.f, 0.f};
#pragma unroll
    for (int i = 0; i < 4; ++i)
#pragma unroll
        for (int j = 0; j < 4; ++j) { accs[i][j] = 0.f; accc[i][j] = 0.f; }

    const int l0 = ch * (L_DIM / NCHUNK);
    for (int lb = 0; lb < L_DIM / NCHUNK; lb += 8) {
        const size_t base = (size_t)(l0 + lb) * 64;
        ks[t] = kp[base + t];  ks[t + 256] = kp[base + t + 256];
        vs[t] = vp[base + t];  vs[t + 256] = vp[base + t + 256];
        __syncthreads();
#pragma unroll
        for (int j = 0; j < 8; ++j) {
            const int l = l0 + lb + j;
            float s, c;
            sincosf(ANG_C * (float)(l + 1), &s, &c);
            const float4 kd = *(const float4*)&ks[j * 64 + d0];
            const float4 vv = *(const float4*)&vs[j * 64 + m0];
            const float kda[4] = {kd.x, kd.y, kd.z, kd.w};
            const float vva[4] = {vv.x, vv.y, vv.z, vv.w};
#pragma unroll
            for (int di = 0; di < 4; ++di) {
                const float kds = kda[di] * s;
                const float kdc = kda[di] * c;
#pragma unroll
                for (int mi = 0; mi < 4; ++mi) {
                    accs[di][mi] += kds * vva[mi];
                    accc[di][mi] += kdc * vva[mi];
                }
                if ((t & 15) == 0) { sas[di] += kds; sac[di] += kdc; }
            }
        }
        __syncthreads();
    }

    float* outp = g_kv_part + (size_t)(h * NCHUNK + ch) * 2 * 4096;
#pragma unroll
    for (int di = 0; di < 4; ++di) {
        *(float4*)&outp[(d0 + di) * 64 + m0] =
            make_float4(accs[di][0], accs[di][1], accs[di][2], accs[di][3]);
        *(float4*)&outp[4096 + (d0 + di) * 64 + m0] =
            make_float4(accc[di][0], accc[di][1], accc[di][2], accc[di][3]);
    }
    if ((t & 15) == 0) {
        float* sp = g_ks_part + (size_t)(h * NCHUNK + ch) * 128;
#pragma unroll
        for (int di = 0; di < 4; ++di) {
            sp[d0 + di] = sas[di];
            sp[64 + d0 + di] = sac[di];
        }
    }
}

// ---------------- Phase 3: out = (sin*q.kvs + cos*q.kvc) / max(sin*q.kss + cos*q.ksc, eps) ----------------
// grid (NH, NCHUNK), 256 threads. kv in smem; 16 l's per iteration, z via 16-lane shfl reduce.
__global__ __launch_bounds__(256, 2) void out_kernel(float* __restrict__ out) {
    const int h = blockIdx.x, ch = blockIdx.y;
    __shared__ float kvs[4096];     // [d*64+m]
    __shared__ float kvc[4096];
    __shared__ float kss[64], ksc[64];
    __shared__ float qs[1024];      // 16 l rows x 64
    __shared__ float zden[16];

    const int t = threadIdx.x;

    // reduce partial kv / ksum
    for (int i = t; i < 4096; i += 256) {
        float ss = 0.f, cc = 0.f;
#pragma unroll
        for (int p = 0; p < NCHUNK; ++p) {
            const float* kp = g_kv_part + (size_t)(h * NCHUNK + p) * 2 * 4096;
            ss += kp[i];
            cc += kp[4096 + i];
        }
        kvs[i] = ss; kvc[i] = cc;
    }
    if (t < 128) {
        float s = 0.f;
#pragma unroll
        for (int p = 0; p < NCHUNK; ++p) s += g_ks_part[(size_t)(h * NCHUNK + p) * 128 + t];
        if (t < 64) kss[t] = s; else ksc[t - 64] = s;
    }
    __syncthreads();

    const float* qp = g_q + (size_t)h * (L_DIM * HD);
    const int bb = h >> 4, hh = h & 15;
    const int li = t >> 6;          // 0..3
    const int m = t & 63;

    const int lend = ch * (L_DIM / NCHUNK) + (L_DIM / NCHUNK);
    for (int l0 = ch * (L_DIM / NCHUNK); l0 < lend; l0 += 16) {
        for (int i = t; i < 1024; i += 256) qs[i] = qp[(size_t)l0 * 64 + i];
        __syncthreads();
        // z denominators, one per l (16 lanes per l, 4 d's each)
        {
            const int l16 = t >> 4;          // 0..15
            const int dg = (t & 15) * 4;
            float s, c;
            sincosf(ANG_C * (float)(l0 + l16 + 1), &s, &c);
            float part = 0.f;
#pragma unroll
            for (int dd = 0; dd < 4; ++dd) {
                const float qd = qs[l16 * 64 + dg + dd];
                part += qd * (s * kss[dg + dd] + c * ksc[dg + dd]);
            }
            part += __shfl_down_sync(0xffffffffu, part, 8, 16);
            part += __shfl_down_sync(0xffffffffu, part, 4, 16);
            part += __shfl_down_sync(0xffffffffu, part, 2, 16);
            part += __shfl_down_sync(0xffffffffu, part, 1, 16);
            if ((t & 15) == 0) zden[l16] = 1.0f / fmaxf(part, EPS_F);
        }
        __syncthreads();

        float accs[4] = {0.f, 0.f, 0.f, 0.f};
        float accc[4] = {0.f, 0.f, 0.f, 0.f};
#pragma unroll
        for (int d4 = 0; d4 < 64; d4 += 4) {
            const float4 q0 = *(const float4*)&qs[(li + 0) * 64 + d4];
            const float4 q1 = *(const float4*)&qs[(li + 4) * 64 + d4];
            const float4 q2 = *(const float4*)&qs[(li + 8) * 64 + d4];
            const float4 q3 = *(const float4*)&qs[(li + 12) * 64 + d4];
            const float qa[4][4] = {{q0.x, q0.y, q0.z, q0.w},
                                    {q1.x, q1.y, q1.z, q1.w},
                                    {q2.x, q2.y, q2.z, q2.w},
                                    {q3.x, q3.y, q3.z, q3.w}};
#pragma unroll
            for (int dd = 0; dd < 4; ++dd) {
                const float kvsv = kvs[(d4 + dd) * 64 + m];
                const float kvcv = kvc[(d4 + dd) * 64 + m];
#pragma unroll
                for (int jj = 0; jj < 4; ++jj) {
                    accs[jj] += qa[jj][dd] * kvsv;
                    accc[jj] += qa[jj][dd] * kvcv;
                }
            }
        }
#pragma unroll
        for (int jj = 0; jj < 4; ++jj) {
            const int lloc = li + jj * 4;
            const int l = l0 + lloc;
            float s, c;
            sincosf(ANG_C * (float)(l + 1), &s, &c);
            const float o = (s * accs[jj] + c * accc[jj]) * zden[lloc];
            out[((size_t)l * B_DIM + bb) * E_DIM + hh * 64 + m] = o;
        }
        __syncthreads();
    }
}

// ---------------- launch ----------------
extern "C" void kernel_launch(void* const* d_in, const int* in_sizes, int n_in,
                              void* d_out, int out_size) {
    const float* q  = (const float*)d_in[0];
    const float* k  = (const float*)d_in[1];
    const float* v  = (const float*)d_in[2];
    const float* Wq = (const float*)d_in[3];
    const float* bq = (const float*)d_in[4];
    const float* Wk = (const float*)d_in[5];
    const float* bk = (const float*)d_in[6];
    const float* Wv = (const float*)d_in[7];
    const float* bv = (const float*)d_in[8];
    float* out = (float*)d_out;

    dim3 g1(E_DIM / 128, M_TOT / 128, 3);   // (8, 128, 3)
    gemm_qkv<<<g1, 256>>>(q, k, v, Wq, Wk, Wv, bq, bk, bv);
    kv_kernel<<<dim3(NH, NCHUNK), 256>>>();
    out_kernel<<<dim3(NH, NCHUNK), 256>>>(out);
}

// round 3
// speedup vs baseline: 1.5745x; 1.5745x over previous
#include <cuda_runtime.h>
#include <cstdint>

#define L_DIM 4096
#define B_DIM 4
#define E_DIM 1024
#define H_DIM 16
#define HD 64
#define NH 64            // B*H
#define M_TOT 16384      // L*B
#define EPS_F 1e-4f
#define ANG_C 3.83495196971410283e-4f   // (pi/2)/4096
#define NCHUNK 8

// ---------------- scratch (device globals; no allocs allowed) ----------------
__device__ float g_q[NH * L_DIM * HD];                 // relu(Q) per head-major
__device__ float g_k[NH * L_DIM * HD];                 // relu(K)
__device__ float g_v[NH * L_DIM * HD];                 // V
__device__ float g_kv_part[NH * NCHUNK * 2 * HD * HD]; // per-chunk partial kv [d128][m64]
__device__ float g_ks_part[NH * NCHUNK * 2 * HD];      // per-chunk partial ksum [d128]
__device__ float g_kv[NH * 2 * HD * HD];               // reduced kv
__device__ float g_ks[NH * 2 * HD];                    // reduced ksum

__device__ __forceinline__ unsigned f2tf32(float x) {
    unsigned r;
    asm("cvt.rna.tf32.f32 %0, %1;" : "=r"(r) : "f"(x));
    return r;
}
__device__ __forceinline__ float ftf(float x) { return __uint_as_float(f2tf32(x)); }

__device__ __forceinline__ void mma_tf32(float c[4],
                                         unsigned a0, unsigned a1, unsigned a2, unsigned a3,
                                         unsigned b0, unsigned b1) {
    asm volatile(
        "mma.sync.aligned.m16n8k8.row.col.f32.tf32.tf32.f32 "
        "{%0,%1,%2,%3}, {%4,%5,%6,%7}, {%8,%9}, {%0,%1,%2,%3};\n"
        : "+f"(c[0]), "+f"(c[1]), "+f"(c[2]), "+f"(c[3])
        : "r"(a0), "r"(a1), "r"(a2), "r"(a3), "r"(b0), "r"(b1));
}

__device__ __forceinline__ void cpa16(void* dst, const void* src) {
    unsigned d = (unsigned)__cvta_generic_to_shared(dst);
    asm volatile("cp.async.cg.shared.global [%0], [%1], 16;\n" :: "r"(d), "l"(src));
}

// ---------------- Phase 1: fused QKV projection (cp.async double-buffered) ----------------
// Y = X @ W^T + b ; X: (M_TOT, E), W: (E, E) row-major. Epilogue: relu + head scatter.
__global__ __launch_bounds__(256, 2) void gemm_qkv(
    const float* __restrict__ Xq, const float* __restrict__ Xk, const float* __restrict__ Xv,
    const float* __restrict__ Wq, const float* __restrict__ Wk, const float* __restrict__ Wv,
    const float* __restrict__ bq, const float* __restrict__ bk, const float* __restrict__ bv)
{
    extern __shared__ float sm1[];   // [2 stages][As 128*36 | Bs 128*36]

    const int z = blockIdx.z;
    const float* X    = (z == 0) ? Xq : (z == 1) ? Xk : Xv;
    const float* W    = (z == 0) ? Wq : (z == 1) ? Wk : Wv;
    const float* bias = (z == 0) ? bq : (z == 1) ? bk : bv;
    float* dst        = (z == 0) ? g_q : (z == 1) ? g_k : g_v;
    const bool do_relu = (z < 2);

    const int m0 = blockIdx.y * 128;
    const int n0 = blockIdx.x * 128;
    const int t = threadIdx.x;
    const int lane = t & 31, warp = t >> 5;
    const int wm = (warp & 1) * 64, wn = (warp >> 1) * 32;
    const int gid = lane >> 2, tig = lane & 3;

    const int lr = t >> 3;          // 0..31
    const int lc = (t & 7) * 4;     // 0..28
    const float* Ag = X + (size_t)(m0 + lr) * E_DIM + lc;
    const float* Bg = W + (size_t)(n0 + lr) * E_DIM + lc;

    float acc[4][4][4];
#pragma unroll
    for (int i = 0; i < 4; ++i)
#pragma unroll
        for (int j = 0; j < 4; ++j)
#pragma unroll
            for (int e = 0; e < 4; ++e) acc[i][j][e] = 0.f;

    auto stage = [&](int kt, int buf) {
        float* sA = sm1 + buf * 9216;
        float* sB = sA + 4608;
#pragma unroll
        for (int i = 0; i < 4; ++i) {
            cpa16(&sA[(lr + i * 32) * 36 + lc], Ag + kt * 32 + (size_t)i * 32 * E_DIM);
            cpa16(&sB[(lr + i * 32) * 36 + lc], Bg + kt * 32 + (size_t)i * 32 * E_DIM);
        }
        asm volatile("cp.async.commit_group;\n");
    };

    stage(0, 0);
#pragma unroll 1
    for (int kt = 0; kt < 32; ++kt) {
        if (kt < 31) {
            stage(kt + 1, (kt + 1) & 1);
            asm volatile("cp.async.wait_group 1;\n");
        } else {
            asm volatile("cp.async.wait_group 0;\n");
        }
        __syncthreads();
        const float* sA = sm1 + (kt & 1) * 9216;
        const float* sB = sA + 4608;
#pragma unroll
        for (int k8 = 0; k8 < 4; ++k8) {
            const int kk = k8 * 8;
            unsigned af[4][4], bf[4][2];
#pragma unroll
            for (int mf = 0; mf < 4; ++mf) {
                const int r = wm + mf * 16 + gid;
                af[mf][0] = f2tf32(sA[r * 36 + kk + tig]);
                af[mf][1] = f2tf32(sA[(r + 8) * 36 + kk + tig]);
                af[mf][2] = f2tf32(sA[r * 36 + kk + tig + 4]);
                af[mf][3] = f2tf32(sA[(r + 8) * 36 + kk + tig + 4]);
            }
#pragma unroll
            for (int nf = 0; nf < 4; ++nf) {
                const int cb = wn + nf * 8 + gid;
                bf[nf][0] = f2tf32(sB[cb * 36 + kk + tig]);
                bf[nf][1] = f2tf32(sB[cb * 36 + kk + tig + 4]);
            }
#pragma unroll
            for (int mf = 0; mf < 4; ++mf)
#pragma unroll
                for (int nf = 0; nf < 4; ++nf)
                    mma_tf32(acc[mf][nf], af[mf][0], af[mf][1], af[mf][2], af[mf][3],
                             bf[nf][0], bf[nf][1]);
        }
        __syncthreads();
    }

    // epilogue: bias + relu + scatter to [head][l][hd]
#pragma unroll
    for (int mf = 0; mf < 4; ++mf) {
#pragma unroll
        for (int nf = 0; nf < 4; ++nf) {
            const int row = m0 + wm + mf * 16 + gid;
            const int col = n0 + wn + nf * 8 + tig * 2;
#pragma unroll
            for (int e = 0; e < 4; ++e) {
                const int r = row + ((e >= 2) ? 8 : 0);
                const int cc = col + (e & 1);
                float v = acc[mf][nf][e] + __ldg(&bias[cc]);
                if (do_relu) v = fmaxf(v, 0.f);
                const int l = r >> 2, bb = r & 3;
                const int hh = cc >> 6, hd = cc & 63;
                const int head = bb * H_DIM + hh;
                dst[((size_t)head << 18) + ((size_t)l << 6) + (size_t)hd] = v;
            }
        }
    }
}

// ---------------- Phase 2: kv = k_^T v via tensor cores ----------------
// Per (head, l-chunk): C[128 d][64 m] += sum_l k_(l,d) * v(l,m); k_ pre-scaled sin/cos.
__global__ __launch_bounds__(256, 2) void kv2() {
    __shared__ float Ks[32 * 136];   // [l][128 scaled d], stride 136
    __shared__ float Vs[32 * 72];    // [l][64 m], stride 72

    const int h = blockIdx.x, ch = blockIdx.y;
    const int t = threadIdx.x, lane = t & 31, warp = t >> 5;
    const int wm = (warp >> 1) * 32, wn = (warp & 1) * 32;
    const int gid = lane >> 2, tig = lane & 3;

    float acc[2][4][4];
#pragma unroll
    for (int mf = 0; mf < 2; ++mf)
#pragma unroll
        for (int nf = 0; nf < 4; ++nf)
#pragma unroll
            for (int e = 0; e < 4; ++e) acc[mf][nf][e] = 0.f;
    float ksacc = 0.f;

    const float* kp = g_k + ((size_t)h << 18);
    const float* vp = g_v + ((size_t)h << 18);
    const int ll = t >> 3;          // 0..31
    const int f = (t & 7) * 8;      // 0..56

#pragma unroll 1
    for (int it = 0; it < 16; ++it) {
        const int lbase = ch * 512 + it * 32;
        {
            const int l = lbase + ll;
            float s, c;
            sincosf(ANG_C * (float)(l + 1), &s, &c);
            const float4 k0 = *(const float4*)(kp + (size_t)l * 64 + f);
            const float4 k1 = *(const float4*)(kp + (size_t)l * 64 + f + 4);
            const float4 v0 = *(const float4*)(vp + (size_t)l * 64 + f);
            const float4 v1 = *(const float4*)(vp + (size_t)l * 64 + f + 4);
            *(float4*)&Ks[ll * 136 + f] =
                make_float4(ftf(k0.x * s), ftf(k0.y * s), ftf(k0.z * s), ftf(k0.w * s));
            *(float4*)&Ks[ll * 136 + f + 4] =
                make_float4(ftf(k1.x * s), ftf(k1.y * s), ftf(k1.z * s), ftf(k1.w * s));
            *(float4*)&Ks[ll * 136 + 64 + f] =
                make_float4(ftf(k0.x * c), ftf(k0.y * c), ftf(k0.z * c), ftf(k0.w * c));
            *(float4*)&Ks[ll * 136 + 64 + f + 4] =
                make_float4(ftf(k1.x * c), ftf(k1.y * c), ftf(k1.z * c), ftf(k1.w * c));
            *(float4*)&Vs[ll * 72 + f] =
                make_float4(ftf(v0.x), ftf(v0.y), ftf(v0.z), ftf(v0.w));
            *(float4*)&Vs[ll * 72 + f + 4] =
                make_float4(ftf(v1.x), ftf(v1.y), ftf(v1.z), ftf(v1.w));
        }
        __syncthreads();
        if (t < 128) {
#pragma unroll
            for (int j = 0; j < 32; ++j) ksacc += Ks[j * 136 + t];
        }
#pragma unroll
        for (int k8 = 0; k8 < 4; ++k8) {
            const int kk = k8 * 8;
            unsigned af[2][4], bf[4][2];
#pragma unroll
            for (int mf = 0; mf < 2; ++mf) {
                const int r = wm + mf * 16 + gid;
                af[mf][0] = __float_as_uint(Ks[(kk + tig) * 136 + r]);
                af[mf][1] = __float_as_uint(Ks[(kk + tig) * 136 + r + 8]);
                af[mf][2] = __float_as_uint(Ks[(kk + tig + 4) * 136 + r]);
                af[mf][3] = __float_as_uint(Ks[(kk + tig + 4) * 136 + r + 8]);
            }
#pragma unroll
            for (int nf = 0; nf < 4; ++nf) {
                const int cb = wn + nf * 8 + gid;
                bf[nf][0] = __float_as_uint(Vs[(kk + tig) * 72 + cb]);
                bf[nf][1] = __float_as_uint(Vs[(kk + tig + 4) * 72 + cb]);
            }
#pragma unroll
            for (int mf = 0; mf < 2; ++mf)
#pragma unroll
                for (int nf = 0; nf < 4; ++nf)
                    mma_tf32(acc[mf][nf], af[mf][0], af[mf][1], af[mf][2], af[mf][3],
                             bf[nf][0], bf[nf][1]);
        }
        __syncthreads();
    }

    float* outp = g_kv_part + (size_t)(h * NCHUNK + ch) * 8192;
#pragma unroll
    for (int mf = 0; mf < 2; ++mf) {
#pragma unroll
        for (int nf = 0; nf < 4; ++nf) {
            const int row = wm + mf * 16 + gid;
            const int col = wn + nf * 8 + tig * 2;
            *(float2*)&outp[row * 64 + col] = make_float2(acc[mf][nf][0], acc[mf][nf][1]);
            *(float2*)&outp[(row + 8) * 64 + col] = make_float2(acc[mf][nf][2], acc[mf][nf][3]);
        }
    }
    if (t < 128) g_ks_part[(size_t)(h * NCHUNK + ch) * 128 + t] = ksacc;
}

// ---------------- Phase 2b: reduce partials ----------------
__global__ __launch_bounds__(256) void reduce_kv() {
    const int h = blockIdx.x, t = threadIdx.x;
    for (int i = t; i < 8192; i += 256) {
        float s = 0.f;
#pragma unroll
        for (int p = 0; p < NCHUNK; ++p) s += g_kv_part[(size_t)(h * NCHUNK + p) * 8192 + i];
        g_kv[(size_t)h * 8192 + i] = s;
    }
    if (t < 128) {
        float s = 0.f;
#pragma unroll
        for (int p = 0; p < NCHUNK; ++p) s += g_ks_part[(size_t)(h * NCHUNK + p) * 128 + t];
        g_ks[h * 128 + t] = s;
    }
}

// ---------------- Phase 3: out = (q_ @ kv) * z via tensor cores ----------------
__global__ __launch_bounds__(256, 1) void out2(float* __restrict__ out) {
    extern __shared__ float sm3[];
    float* KVs  = sm3;                     // [128 d][64 m] stride 72  -> 9216 floats
    float* Qs   = sm3 + 9216;              // [128 l][128 d] stride 140 -> 17920 floats
    float* kss  = sm3 + 9216 + 17920;      // [128]
    float* zden = kss + 128;               // [128]

    const int h = blockIdx.x, ch = blockIdx.y;
    const int t = threadIdx.x, lane = t & 31, warp = t >> 5;
    const int wm = (warp >> 1) * 32, wn = (warp & 1) * 32;
    const int gid = lane >> 2, tig = lane & 3;

    for (int i = t; i < 8192; i += 256) {
        const int r = i >> 6, cn = i & 63;
        KVs[r * 72 + cn] = ftf(g_kv[(size_t)h * 8192 + i]);
    }
    if (t < 128) kss[t] = g_ks[h * 128 + t];

    const float* qp = g_q + ((size_t)h << 18);
    const int bb = h >> 4, hh = h & 15;
    const int lq = t >> 1;            // 0..127
    const int fq = (t & 1) * 32;      // 0 or 32

#pragma unroll 1
    for (int it = 0; it < 4; ++it) {
        __syncthreads();
        const int l0 = ch * 512 + it * 128;
        {
            const int l = l0 + lq;
            float s, c;
            sincosf(ANG_C * (float)(l + 1), &s, &c);
            const float* qrow = qp + (size_t)l * 64 + fq;
#pragma unroll
            for (int j = 0; j < 8; ++j) {
                const float4 qv = *(const float4*)(qrow + j * 4);
                *(float4*)&Qs[lq * 140 + fq + j * 4] =
                    make_float4(ftf(qv.x * s), ftf(qv.y * s), ftf(qv.z * s), ftf(qv.w * s));
                *(float4*)&Qs[lq * 140 + 64 + fq + j * 4] =
                    make_float4(ftf(qv.x * c), ftf(qv.y * c), ftf(qv.z * c), ftf(qv.w * c));
            }
        }
        __syncthreads();
        {
            const int lz = t >> 1;
            const int half = (t & 1) * 64;
            float p = 0.f;
#pragma unroll
            for (int d = 0; d < 64; ++d) p += Qs[lz * 140 + half + d] * kss[half + d];
            p += __shfl_xor_sync(0xffffffffu, p, 1);
            if ((t & 1) == 0) zden[lz] = 1.0f / fmaxf(p, EPS_F);
        }
        __syncthreads();

        float acc[2][4][4];
#pragma unroll
        for (int mf = 0; mf < 2; ++mf)
#pragma unroll
            for (int nf = 0; nf < 4; ++nf)
#pragma unroll
                for (int e = 0; e < 4; ++e) acc[mf][nf][e] = 0.f;

#pragma unroll
        for (int k8 = 0; k8 < 16; ++k8) {
            const int kk = k8 * 8;
            unsigned af[2][4], bf[4][2];
#pragma unroll
            for (int mf = 0; mf < 2; ++mf) {
                const int r = wm + mf * 16 + gid;
                af[mf][0] = __float_as_uint(Qs[r * 140 + kk + tig]);
                af[mf][1] = __float_as_uint(Qs[(r + 8) * 140 + kk + tig]);
                af[mf][2] = __float_as_uint(Qs[r * 140 + kk + tig + 4]);
                af[mf][3] = __float_as_uint(Qs[(r + 8) * 140 + kk + tig + 4]);
            }
#pragma unroll
            for (int nf = 0; nf < 4; ++nf) {
                const int cb = wn + nf * 8 + gid;
                bf[nf][0] = __float_as_uint(KVs[(kk + tig) * 72 + cb]);
                bf[nf][1] = __float_as_uint(KVs[(kk + tig + 4) * 72 + cb]);
            }
#pragma unroll
            for (int mf = 0; mf < 2; ++mf)
#pragma unroll
                for (int nf = 0; nf < 4; ++nf)
                    mma_tf32(acc[mf][nf], af[mf][0], af[mf][1], af[mf][2], af[mf][3],
                             bf[nf][0], bf[nf][1]);
        }

#pragma unroll
        for (int mf = 0; mf < 2; ++mf) {
#pragma unroll
            for (int nf = 0; nf < 4; ++nf) {
                const int rl = wm + mf * 16 + gid;
                const int col = hh * 64 + wn + nf * 8 + tig * 2;
                const float z0 = zden[rl];
                const float z1 = zden[rl + 8];
                const int l_a = l0 + rl;
                const int l_b = l_a + 8;
                *(float2*)&out[((size_t)l_a * B_DIM + bb) * E_DIM + col] =
                    make_float2(acc[mf][nf][0] * z0, acc[mf][nf][1] * z0);
                *(float2*)&out[((size_t)l_b * B_DIM + bb) * E_DIM + col] =
                    make_float2(acc[mf][nf][2] * z1, acc[mf][nf][3] * z1);
            }
        }
    }
}

// ---------------- launch ----------------
extern "C" void kernel_launch(void* const* d_in, const int* in_sizes, int n_in,
                              void* d_out, int out_size) {
    const float* q  = (const float*)d_in[0];
    const float* k  = (const float*)d_in[1];
    const float* v  = (const float*)d_in[2];
    const float* Wq = (const float*)d_in[3];
    const float* bq = (const float*)d_in[4];
    const float* Wk = (const float*)d_in[5];
    const float* bk = (const float*)d_in[6];
    const float* Wv = (const float*)d_in[7];
    const float* bv = (const float*)d_in[8];
    float* out = (float*)d_out;

    const int smem1 = 2 * 9216 * 4;                         // 73728 B
    const int smem3 = (9216 + 17920 + 256) * 4;             // 109568 B
    cudaFuncSetAttribute(gemm_qkv, cudaFuncAttributeMaxDynamicSharedMemorySize, smem1);
    cudaFuncSetAttribute(out2, cudaFuncAttributeMaxDynamicSharedMemorySize, smem3);

    dim3 g1(E_DIM / 128, M_TOT / 128, 3);   // (8, 128, 3)
    gemm_qkv<<<g1, 256, smem1>>>(q, k, v, Wq, Wk, Wv, bq, bk, bv);
    kv2<<<dim3(NH, NCHUNK), 256>>>();
    reduce_kv<<<NH, 256>>>();
    out2<<<dim3(NH, NCHUNK), 256, smem3>>>(out);
}

// round 5
// speedup vs baseline: 1.6217x; 1.0300x over previous
#include <cuda_runtime.h>
#include <cstdint>

#define L_DIM 4096
#define B_DIM 4
#define E_DIM 1024
#define H_DIM 16
#define HD 64
#define NH 64            // B*H
#define M_TOT 16384      // L*B
#define EPS_F 1e-4f
#define ANG_C 3.83495196971410283e-4f   // (pi/2)/4096
#define NCHUNK 8

// ---------------- scratch (device globals; no allocs allowed) ----------------
__device__ float g_q[NH * L_DIM * HD];                 // relu(Q) per head-major
__device__ float g_k[NH * L_DIM * HD];                 // relu(K)
__device__ float g_v[NH * L_DIM * HD];                 // V
__device__ float g_xr[3 * M_TOT * E_DIM];              // RNA-rounded, K-permuted X (q,k,v)
__device__ float g_wr[3 * E_DIM * E_DIM];              // RNA-rounded, K-permuted W (q,k,v)
__device__ float g_kv_part[NH * NCHUNK * 2 * HD * HD]; // per-chunk partial kv [d128][m64]
__device__ float g_ks_part[NH * NCHUNK * 2 * HD];      // per-chunk partial ksum [d128]
__device__ float g_kv[NH * 2 * HD * HD];               // reduced kv
__device__ float g_ks[NH * 2 * HD];                    // reduced ksum

__device__ __forceinline__ unsigned f2tf32(float x) {
    unsigned r;
    asm("cvt.rna.tf32.f32 %0, %1;" : "=r"(r) : "f"(x));
    return r;
}
__device__ __forceinline__ float ftf(float x) { return __uint_as_float(f2tf32(x)); }

__device__ __forceinline__ void mma_tf32(float c[4],
                                         unsigned a0, unsigned a1, unsigned a2, unsigned a3,
                                         unsigned b0, unsigned b1) {
    asm volatile(
        "mma.sync.aligned.m16n8k8.row.col.f32.tf32.tf32.f32 "
        "{%0,%1,%2,%3}, {%4,%5,%6,%7}, {%8,%9}, {%0,%1,%2,%3};\n"
        : "+f"(c[0]), "+f"(c[1]), "+f"(c[2]), "+f"(c[3])
        : "r"(a0), "r"(a1), "r"(a2), "r"(a3), "r"(b0), "r"(b1));
}

__device__ __forceinline__ void cpa16(void* dst, const void* src) {
    unsigned d = (unsigned)__cvta_generic_to_shared(dst);
    asm volatile("cp.async.cg.shared.global [%0], [%1], 16;\n" :: "r"(d), "l"(src));
}

// ---------------- Phase 0: RNA-round + K-permute X and W ----------------
// 8-col group [k0..k7] -> [k0,k4,k1,k5,k2,k6,k3,k7] so tf32 frag pairs (k, k+4)
// are adjacent -> one LDS.64 per fragment pair, no CVT in mainloop.
__global__ __launch_bounds__(256) void preround_x(const float4* __restrict__ xq,
                                                  const float4* __restrict__ xk,
                                                  const float4* __restrict__ xv) {
    const int g = blockIdx.x * 256 + threadIdx.x;     // group id, 8 floats each
    const int z = blockIdx.y;
    const float4* src = (z == 0) ? xq : (z == 1) ? xk : xv;
    const float4 g0 = src[2 * g], g1 = src[2 * g + 1];
    float4* dst = (float4*)g_xr + (size_t)z * 4194304 + 2 * g;
    dst[0] = make_float4(ftf(g0.x), ftf(g1.x), ftf(g0.y), ftf(g1.y));
    dst[1] = make_float4(ftf(g0.z), ftf(g1.z), ftf(g0.w), ftf(g1.w));
}

__global__ __launch_bounds__(256) void preround_w(const float4* __restrict__ wq,
                                                  const float4* __restrict__ wk,
                                                  const float4* __restrict__ wv) {
    const int g = blockIdx.x * 256 + threadIdx.x;
    const int z = blockIdx.y;
    const float4* src = (z == 0) ? wq : (z == 1) ? wk : wv;
    const float4 g0 = src[2 * g], g1 = src[2 * g + 1];
    float4* dst = (float4*)g_wr + (size_t)z * 262144 + 2 * g;
    dst[0] = make_float4(ftf(g0.x), ftf(g1.x), ftf(g0.y), ftf(g1.y));
    dst[1] = make_float4(ftf(g0.z), ftf(g1.z), ftf(g0.w), ftf(g1.w));
}

// ---------------- Phase 1: fused QKV projection ----------------
// 128x128 CTA tile, 64x32 warptile, cp.async double buffer, smem stride 40.
#define SSTR 40
#define STG_F (128 * SSTR)           // floats per matrix per stage (5120)

__global__ __launch_bounds__(256, 2) void gemm_qkv(
    const float* __restrict__ bq, const float* __restrict__ bk, const float* __restrict__ bv)
{
    extern __shared__ float sm1[];   // [2 stages][A 5120 | B 5120]

    const int z = blockIdx.z;
    const float* X    = g_xr + (size_t)z * (M_TOT * E_DIM);
    const float* W    = g_wr + (size_t)z * (E_DIM * E_DIM);
    const float* bias = (z == 0) ? bq : (z == 1) ? bk : bv;
    float* dst        = (z == 0) ? g_q : (z == 1) ? g_k : g_v;
    const bool do_relu = (z < 2);

    const int m0 = blockIdx.y * 128;
    const int n0 = blockIdx.x * 128;
    const int t = threadIdx.x;
    const int lane = t & 31, warp = t >> 5;
    const int wm = (warp & 1) * 64, wn = (warp >> 1) * 32;
    const int gid = lane >> 2, tig = lane & 3;

    const int lr = t >> 3;          // 0..31
    const int lc = (t & 7) * 4;     // 0..28
    const float* Ag = X + (size_t)(m0 + lr) * E_DIM + lc;
    const float* Bg = W + (size_t)(n0 + lr) * E_DIM + lc;

    float acc[4][4][4];
#pragma unroll
    for (int i = 0; i < 4; ++i)
#pragma unroll
        for (int j = 0; j < 4; ++j)
#pragma unroll
            for (int e = 0; e < 4; ++e) acc[i][j][e] = 0.f;

    auto stage = [&](int kt, int buf) {
        float* sA = sm1 + buf * (2 * STG_F);
        float* sB = sA + STG_F;
#pragma unroll
        for (int i = 0; i < 4; ++i) {
            cpa16(&sA[(lr + i * 32) * SSTR + lc], Ag + kt * 32 + (size_t)i * 32 * E_DIM);
            cpa16(&sB[(lr + i * 32) * SSTR + lc], Bg + kt * 32 + (size_t)i * 32 * E_DIM);
        }
        asm volatile("cp.async.commit_group;\n");
    };

    stage(0, 0);
#pragma unroll 1
    for (int kt = 0; kt < 32; ++kt) {
        if (kt < 31) {
            stage(kt + 1, (kt + 1) & 1);
            asm volatile("cp.async.wait_group 1;\n");
        } else {
            asm volatile("cp.async.wait_group 0;\n");
        }
        __syncthreads();
        const float* sA = sm1 + (kt & 1) * (2 * STG_F);
        const float* sB = sA + STG_F;
#pragma unroll
        for (int k8 = 0; k8 < 4; ++k8) {
            const int kk = k8 * 8;
            float2 aA[4][2];
            float2 bB[4];
#pragma unroll
            for (int mf = 0; mf < 4; ++mf) {
                const int r = wm + mf * 16 + gid;
                aA[mf][0] = *(const float2*)&sA[r * SSTR + kk + tig * 2];
                aA[mf][1] = *(const float2*)&sA[(r + 8) * SSTR + kk + tig * 2];
            }
#pragma unroll
            for (int nf = 0; nf < 4; ++nf) {
                const int cb = wn + nf * 8 + gid;
                bB[nf] = *(const float2*)&sB[cb * SSTR + kk + tig * 2];
            }
#pragma unroll
            for (int mf = 0; mf < 4; ++mf)
#pragma unroll
                for (int nf = 0; nf < 4; ++nf)
                    mma_tf32(acc[mf][nf],
                             __float_as_uint(aA[mf][0].x), __float_as_uint(aA[mf][1].x),
                             __float_as_uint(aA[mf][0].y), __float_as_uint(aA[mf][1].y),
                             __float_as_uint(bB[nf].x),    __float_as_uint(bB[nf].y));
        }
        __syncthreads();
    }

    // epilogue: bias + relu + scatter to [head][l][hd]
#pragma unroll
    for (int mf = 0; mf < 4; ++mf) {
#pragma unroll
        for (int nf = 0; nf < 4; ++nf) {
            const int row = m0 + wm + mf * 16 + gid;
            const int col = n0 + wn + nf * 8 + tig * 2;
#pragma unroll
            for (int e = 0; e < 4; ++e) {
                const int r = row + ((e >= 2) ? 8 : 0);
                const int cc = col + (e & 1);
                float v = acc[mf][nf][e] + __ldg(&bias[cc]);
                if (do_relu) v = fmaxf(v, 0.f);
                const int l = r >> 2, bb = r & 3;
                const int hh = cc >> 6, hd = cc & 63;
                const int head = bb * H_DIM + hh;
                dst[((size_t)head << 18) + ((size_t)l << 6) + (size_t)hd] = v;
            }
        }
    }
}

// ---------------- Phase 2: kv = k_^T v via tensor cores ----------------
__global__ __launch_bounds__(256, 2) void kv2() {
    __shared__ float Ks[32 * 136];   // [l][128 scaled d], stride 136
    __shared__ float Vs[32 * 72];    // [l][64 m], stride 72

    const int h = blockIdx.x, ch = blockIdx.y;
    const int t = threadIdx.x, lane = t & 31, warp = t >> 5;
    const int wm = (warp >> 1) * 32, wn = (warp & 1) * 32;
    const int gid = lane >> 2, tig = lane & 3;

    float acc[2][4][4];
#pragma unroll
    for (int mf = 0; mf < 2; ++mf)
#pragma unroll
        for (int nf = 0; nf < 4; ++nf)
#pragma unroll
            for (int e = 0; e < 4; ++e) acc[mf][nf][e] = 0.f;
    float ksacc = 0.f;

    const float* kp = g_k + ((size_t)h << 18);
    const float* vp = g_v + ((size_t)h << 18);
    const int ll = t >> 3;
    const int f = (t & 7) * 8;

#pragma unroll 1
    for (int it = 0; it < 16; ++it) {
        const int lbase = ch * 512 + it * 32;
        {
            const int l = lbase + ll;
            float s, c;
            sincosf(ANG_C * (float)(l + 1), &s, &c);
            const float4 k0 = *(const float4*)(kp + (size_t)l * 64 + f);
            const float4 k1 = *(const float4*)(kp + (size_t)l * 64 + f + 4);
            const float4 v0 = *(const float4*)(vp + (size_t)l * 64 + f);
            const float4 v1 = *(const float4*)(vp + (size_t)l * 64 + f + 4);
            *(float4*)&Ks[ll * 136 + f] =
                make_float4(ftf(k0.x * s), ftf(k0.y * s), ftf(k0.z * s), ftf(k0.w * s));
            *(float4*)&Ks[ll * 136 + f + 4] =
                make_float4(ftf(k1.x * s), ftf(k1.y * s), ftf(k1.z * s), ftf(k1.w * s));
            *(float4*)&Ks[ll * 136 + 64 + f] =
                make_float4(ftf(k0.x * c), ftf(k0.y * c), ftf(k0.z * c), ftf(k0.w * c));
            *(float4*)&Ks[ll * 136 + 64 + f + 4] =
                make_float4(ftf(k1.x * c), ftf(k1.y * c), ftf(k1.z * c), ftf(k1.w * c));
            *(float4*)&Vs[ll * 72 + f] =
                make_float4(ftf(v0.x), ftf(v0.y), ftf(v0.z), ftf(v0.w));
            *(float4*)&Vs[ll * 72 + f + 4] =
                make_float4(ftf(v1.x), ftf(v1.y), ftf(v1.z), ftf(v1.w));
        }
        __syncthreads();
        if (t < 128) {
#pragma unroll
            for (int j = 0; j < 32; ++j) ksacc += Ks[j * 136 + t];
        }
#pragma unroll
        for (int k8 = 0; k8 < 4; ++k8) {
            const int kk = k8 * 8;
            unsigned af[2][4], bf[4][2];
#pragma unroll
            for (int mf = 0; mf < 2; ++mf) {
                const int r = wm + mf * 16 + gid;
                af[mf][0] = __float_as_uint(Ks[(kk + tig) * 136 + r]);
                af[mf][1] = __float_as_uint(Ks[(kk + tig) * 136 + r + 8]);
                af[mf][2] = __float_as_uint(Ks[(kk + tig + 4) * 136 + r]);
                af[mf][3] = __float_as_uint(Ks[(kk + tig + 4) * 136 + r + 8]);
            }
#pragma unroll
            for (int nf = 0; nf < 4; ++nf) {
                const int cb = wn + nf * 8 + gid;
                bf[nf][0] = __float_as_uint(Vs[(kk + tig) * 72 + cb]);
                bf[nf][1] = __float_as_uint(Vs[(kk + tig + 4) * 72 + cb]);
            }
#pragma unroll
            for (int mf = 0; mf < 2; ++mf)
#pragma unroll
                for (int nf = 0; nf < 4; ++nf)
                    mma_tf32(acc[mf][nf], af[mf][0], af[mf][1], af[mf][2], af[mf][3],
                             bf[nf][0], bf[nf][1]);
        }
        __syncthreads();
    }

    float* outp = g_kv_part + (size_t)(h * NCHUNK + ch) * 8192;
#pragma unroll
    for (int mf = 0; mf < 2; ++mf) {
#pragma unroll
        for (int nf = 0; nf < 4; ++nf) {
            const int row = wm + mf * 16 + gid;
            const int col = wn + nf * 8 + tig * 2;
            *(float2*)&outp[row * 64 + col] = make_float2(acc[mf][nf][0], acc[mf][nf][1]);
            *(float2*)&outp[(row + 8) * 64 + col] = make_float2(acc[mf][nf][2], acc[mf][nf][3]);
        }
    }
    if (t < 128) g_ks_part[(size_t)(h * NCHUNK + ch) * 128 + t] = ksacc;
}

// ---------------- Phase 2b: reduce partials ----------------
__global__ __launch_bounds__(256) void reduce_kv() {
    const int h = blockIdx.x, t = threadIdx.x;
    for (int i = t; i < 8192; i += 256) {
        float s = 0.f;
#pragma unroll
        for (int p = 0; p < NCHUNK; ++p) s += g_kv_part[(size_t)(h * NCHUNK + p) * 8192 + i];
        g_kv[(size_t)h * 8192 + i] = s;
    }
    if (t < 128) {
        float s = 0.f;
#pragma unroll
        for (int p = 0; p < NCHUNK; ++p) s += g_ks_part[(size_t)(h * NCHUNK + p) * 128 + t];
        g_ks[h * 128 + t] = s;
    }
}

// ---------------- Phase 3: out = (q_ @ kv) * z via tensor cores ----------------
__global__ __launch_bounds__(256, 1) void out2(float* __restrict__ out) {
    extern __shared__ float sm3[];
    float* KVs  = sm3;                     // [128 d][64 m] stride 72  -> 9216 floats
    float* Qs   = sm3 + 9216;              // [128 l][128 d] stride 140 -> 17920 floats
    float* kss  = sm3 + 9216 + 17920;      // [128]
    float* zden = kss + 128;               // [128]

    const int h = blockIdx.x, ch = blockIdx.y;
    const int t = threadIdx.x, lane = t & 31, warp = t >> 5;
    const int wm = (warp >> 1) * 32, wn = (warp & 1) * 32;
    const int gid = lane >> 2, tig = lane & 3;

    for (int i = t; i < 8192; i += 256) {
        const int r = i >> 6, cn = i & 63;
        KVs[r * 72 + cn] = ftf(g_kv[(size_t)h * 8192 + i]);
    }
    if (t < 128) kss[t] = g_ks[h * 128 + t];

    const float* qp = g_q + ((size_t)h << 18);
    const int bb = h >> 4, hh = h & 15;

#pragma unroll 1
    for (int it = 0; it < 4; ++it) {
        __syncthreads();
        const int l0 = ch * 512 + it * 128;
        {
            const int lq = t >> 1;
            const int fq = (t & 1) * 32;
            const int l = l0 + lq;
            float s, c;
            sincosf(ANG_C * (float)(l + 1), &s, &c);
            const float* qrow = qp + (size_t)l * 64 + fq;
#pragma unroll
            for (int j = 0; j < 8; ++j) {
                const float4 qv = *(const float4*)(qrow + j * 4);
                *(float4*)&Qs[lq * 140 + fq + j * 4] =
                    make_float4(ftf(qv.x * s), ftf(qv.y * s), ftf(qv.z * s), ftf(qv.w * s));
                *(float4*)&Qs[lq * 140 + 64 + fq + j * 4] =
                    make_float4(ftf(qv.x * c), ftf(qv.y * c), ftf(qv.z * c), ftf(qv.w * c));
            }
        }
        __syncthreads();
        {
            const int lz = t >> 1;
            const int half = (t & 1) * 64;
            float p = 0.f;
#pragma unroll
            for (int d = 0; d < 64; ++d) p += Qs[lz * 140 + half + d] * kss[half + d];
            p += __shfl_xor_sync(0xffffffffu, p, 1);
            if ((t & 1) == 0) zden[lz] = 1.0f / fmaxf(p, EPS_F);
        }
        __syncthreads();

        float acc[2][4][4];
#pragma unroll
        for (int mf = 0; mf < 2; ++mf)
#pragma unroll
            for (int nf = 0; nf < 4; ++nf)
#pragma unroll
                for (int e = 0; e < 4; ++e) acc[mf][nf][e] = 0.f;

#pragma unroll
        for (int k8 = 0; k8 < 16; ++k8) {
            const int kk = k8 * 8;
            unsigned af[2][4], bf[4][2];
#pragma unroll
            for (int mf = 0; mf < 2; ++mf) {
                const int r = wm + mf * 16 + gid;
                af[mf][0] = __float_as_uint(Qs[r * 140 + kk + tig]);
                af[mf][1] = __float_as_uint(Qs[(r + 8) * 140 + kk + tig]);
                af[mf][2] = __float_as_uint(Qs[r * 140 + kk + tig + 4]);
                af[mf][3] = __float_as_uint(Qs[(r + 8) * 140 + kk + tig + 4]);
            }
#pragma unroll
            for (int nf = 0; nf < 4; ++nf) {
                const int cb = wn + nf * 8 + gid;
                bf[nf][0] = __float_as_uint(KVs[(kk + tig) * 72 + cb]);
                bf[nf][1] = __float_as_uint(KVs[(kk + tig + 4) * 72 + cb]);
            }
#pragma unroll
            for (int mf = 0; mf < 2; ++mf)
#pragma unroll
                for (int nf = 0; nf < 4; ++nf)
                    mma_tf32(acc[mf][nf], af[mf][0], af[mf][1], af[mf][2], af[mf][3],
                             bf[nf][0], bf[nf][1]);
        }

#pragma unroll
        for (int mf = 0; mf < 2; ++mf) {
#pragma unroll
            for (int nf = 0; nf < 4; ++nf) {
                const int rl = wm + mf * 16 + gid;
                const int col = hh * 64 + wn + nf * 8 + tig * 2;
                const float z0 = zden[rl];
                const float z1 = zden[rl + 8];
                const int l_a = l0 + rl;
                const int l_b = l_a + 8;
                *(float2*)&out[((size_t)l_a * B_DIM + bb) * E_DIM + col] =
                    make_float2(acc[mf][nf][0] * z0, acc[mf][nf][1] * z0);
                *(float2*)&out[((size_t)l_b * B_DIM + bb) * E_DIM + col] =
                    make_float2(acc[mf][nf][2] * z1, acc[mf][nf][3] * z1);
            }
        }
    }
}

// ---------------- launch ----------------
extern "C" void kernel_launch(void* const* d_in, const int* in_sizes, int n_in,
                              void* d_out, int out_size) {
    const float* q  = (const float*)d_in[0];
    const float* k  = (const float*)d_in[1];
    const float* v  = (const float*)d_in[2];
    const float* Wq = (const float*)d_in[3];
    const float* bq = (const float*)d_in[4];
    const float* Wk = (const float*)d_in[5];
    const float* bk = (const float*)d_in[6];
    const float* Wv = (const float*)d_in[7];
    const float* bv = (const float*)d_in[8];
    float* out = (float*)d_out;

    const int smem1 = 2 * 2 * STG_F * 4;                    // 81920 B
    const int smem3 = (9216 + 17920 + 256) * 4;             // 109568 B
    cudaFuncSetAttribute(gemm_qkv, cudaFuncAttributeMaxDynamicSharedMemorySize, smem1);
    cudaFuncSetAttribute(out2, cudaFuncAttributeMaxDynamicSharedMemorySize, smem3);

    preround_x<<<dim3(8192, 3), 256>>>((const float4*)q, (const float4*)k, (const float4*)v);
    preround_w<<<dim3(512, 3), 256>>>((const float4*)Wq, (const float4*)Wk, (const float4*)Wv);
    dim3 g1(E_DIM / 128, M_TOT / 128, 3);   // (8, 128, 3)
    gemm_qkv<<<g1, 256, smem1>>>(bq, bk, bv);
    kv2<<<dim3(NH, NCHUNK), 256>>>();
    reduce_kv<<<NH, 256>>>();
    out2<<<dim3(NH, NCHUNK), 256, smem3>>>(out);
}